// round 13
// baseline (speedup 1.0000x reference)
#include <cuda_runtime.h>
#include <cstdint>

#define NT      9
#define SEQ     512
#define BATCH   64
#define EMB     1024
#define NQ      4
#define CHUNK_LEN 16
#define CPB     8
#define EMP     12

#define L2E 1.4426950408889634f
#define LN2 0.6931471805599453f

__device__ float g_M[BATCH * NQ * 81];
__device__ float g_num[BATCH];
__device__ int   g_cnt[BATCH];
__device__ int   g_qtick[BATCH * NQ];
__device__ int   g_btick[BATCH];
__device__ float g_bll[BATCH];
__device__ int   g_done;

__device__ __forceinline__ void ffma2(unsigned long long& acc,
                                      unsigned long long a,
                                      unsigned long long b)
{
    asm("fma.rn.f32x2 %0, %1, %2, %3;" : "=l"(acc) : "l"(a), "l"(b), "l"(acc));
}
__device__ __forceinline__ unsigned long long dup2(float x)
{
    unsigned long long r; asm("mov.b64 %0, {%1,%1};" : "=l"(r) : "f"(x)); return r;
}
__device__ __forceinline__ float fast_ex2(float x)
{
    float r; asm("ex2.approx.ftz.f32 %0, %1;" : "=f"(r) : "f"(x)); return r;
}
__device__ __forceinline__ float fast_lg2(float x)
{
    float r; asm("lg2.approx.ftz.f32 %0, %1;" : "=f"(r) : "f"(x)); return r;
}

// ---------------------------------------------------------------------------
// Fused kernel: emis6 body (proven) + ticket-gated CRF quarter scans +
// per-batch finalize + global log-likelihood sum. grid 1024 x 128.
// Batch b = blocks 16b..16b+15; quarter qq = 4 consecutive blocks.
// All ticket counters self-reset each run (graph-replay safe).
// ---------------------------------------------------------------------------
__global__ __launch_bounds__(128, 6) void emis_crf(
    const float* __restrict__ embed,
    const float* __restrict__ W,
    const float* __restrict__ bias,
    const unsigned* __restrict__ tags_words,
    const int*  __restrict__ mask,
    const float* __restrict__ startT,
    const float* __restrict__ endT,
    const float* __restrict__ trans,
    float* __restrict__ out)
{
    __shared__ __align__(16) float buf[4608];   // 18 KB, shared by both phases
    __shared__ int   s_flag;     // this block runs the quarter scan
    __shared__ float s_accf;
    __shared__ int   s_msum, s_last, s_any, s_fin;

    const int tid = threadIdx.x;

    // ======================= phase A: emis6 (verbatim) =======================
    {
        float* sE  = buf;            // 32*68 staging / 32*73 reduction
        float* sWt = buf + 2336;     // 64*12

        const int q = tid >> 5;
        const int r = tid & 31;
        const int rowBase = blockIdx.x * 32;

        float4 pe[4];
        float  pw[5];
        {
            const float* gsrc = embed + (size_t)rowBase * EMB;
#pragma unroll
            for (int it = 0; it < 4; ++it) {
                int idx = it * 128 + tid;
                int r2 = idx >> 4, cc = (idx & 15) * 4;
                pe[it] = *(const float4*)(gsrc + (size_t)r2 * EMB + cc);
            }
#pragma unroll
            for (int it = 0; it < 5; ++it) {
                int idx = it * 128 + tid;
                if (idx < 576) {
                    int t = idx >> 6, e = idx & 63;
                    pw[it] = W[t * EMB + e];
                }
            }
        }

        unsigned long long a01 = 0ull, a23 = 0ull, a45 = 0ull, a67 = 0ull;
        float a8 = 0.0f;

        for (int tile = 0; tile < 16; ++tile) {
            __syncthreads();
#pragma unroll
            for (int it = 0; it < 4; ++it) {
                int idx = it * 128 + tid;
                int r2 = idx >> 4, cc = (idx & 15) * 4;
                *(float4*)&sE[r2 * 68 + cc] = pe[it];
            }
#pragma unroll
            for (int it = 0; it < 5; ++it) {
                int idx = it * 128 + tid;
                if (idx < 576) {
                    int t = idx >> 6, e = idx & 63;
                    sWt[e * 12 + t] = pw[it];
                }
            }
            __syncthreads();

            if (tile < 15) {
                const float* gsrc = embed + (size_t)rowBase * EMB + (tile + 1) * 64;
#pragma unroll
                for (int it = 0; it < 4; ++it) {
                    int idx = it * 128 + tid;
                    int r2 = idx >> 4, cc = (idx & 15) * 4;
                    pe[it] = *(const float4*)(gsrc + (size_t)r2 * EMB + cc);
                }
#pragma unroll
                for (int it = 0; it < 5; ++it) {
                    int idx = it * 128 + tid;
                    if (idx < 576) {
                        int t = idx >> 6, e = idx & 63;
                        pw[it] = W[t * EMB + (tile + 1) * 64 + e];
                    }
                }
            }

            const float* xr = &sE[r * 68 + q * 16];
            const float* wq = &sWt[(q * 16) * 12];
#pragma unroll
            for (int e4 = 0; e4 < 16; e4 += 4) {
                float4 x = *(const float4*)(xr + e4);
#pragma unroll
                for (int u = 0; u < 4; ++u) {
                    float xs = (u == 0) ? x.x : (u == 1) ? x.y : (u == 2) ? x.z : x.w;
                    const float* we = wq + (e4 + u) * 12;
                    ulonglong2 wA = *(const ulonglong2*)we;
                    ulonglong2 wB = *(const ulonglong2*)(we + 4);
                    float w8 = we[8];
                    unsigned long long dx = dup2(xs);
                    ffma2(a01, dx, wA.x); ffma2(a23, dx, wA.y);
                    ffma2(a45, dx, wB.x); ffma2(a67, dx, wB.y);
                    a8 = fmaf(xs, w8, a8);
                }
            }
        }

        __syncthreads();
        float* red = sE;
        {
            float2 f;
            float* rp = &red[r * 37 + q * 9];
            f = *(float2*)&a01; rp[0] = f.x; rp[1] = f.y;
            f = *(float2*)&a23; rp[2] = f.x; rp[3] = f.y;
            f = *(float2*)&a45; rp[4] = f.x; rp[5] = f.y;
            f = *(float2*)&a67; rp[6] = f.x; rp[7] = f.y;
            rp[8] = a8;
        }
        __syncthreads();

        if (tid < 32) {
            const float* rp = &red[tid * 37];
            float acc[NT];
#pragma unroll
            for (int t = 0; t < NT; t++)
                acc[t] = rp[t] + rp[9 + t] + rp[18 + t] + rp[27 + t] + bias[t];

            float mx = acc[0];
#pragma unroll
            for (int t = 1; t < NT; t++) mx = fmaxf(mx, acc[t]);
            float sum = 0.0f;
#pragma unroll
            for (int t = 0; t < NT; t++) sum += fast_ex2((acc[t] - mx) * L2E);
            float lse = fmaf(fast_lg2(sum), LN2, mx);

            float* o = out + 1 + (size_t)(rowBase + tid) * NT;
#pragma unroll
            for (int t = 0; t < NT; t++) o[t] = acc[t] - lse;
        }
    }

    // =================== ticket: 4th block of a quarter scans ===============
    const int b  = blockIdx.x >> 4;
    const int qq = (blockIdx.x >> 2) & 3;

    __syncthreads();                 // all emission stores executed
    if (tid == 0) {
        __threadfence();             // release emission stores
        int old = atomicAdd(&g_qtick[b * NQ + qq], 1);
        s_flag = (old == 3);
        s_accf = 0.0f; s_msum = 0; s_any = 0;
    }
    __syncthreads();
    if (!s_flag) return;

    // ======================= phase B: quarter CRF scan ======================
    __threadfence();                 // acquire emissions of this quarter
    const float* emis = out + 1;
    const float* em_b = emis + (size_t)b * SEQ * NT;

    float* sEm = buf;                        // 128*12
    float* sEx = buf + 1536;                 // 128*12
    int*   sMk = (int*)(buf + 3072);         // 128
    float* sTr = buf + 3200;                 // 96
    float* sE2 = buf + 3296;                 // 112  exp(trans) [k][12]
    float* sMt = buf + 3408;                 // 8*84 chunk matrices
    float* sEB = buf + 4080;                 // 4*112

    const int t0 = (qq == 0) ? 1 : qq * 128;
    const int n  = (qq == 0) ? 127 : 128;

    const float* em_q = em_b + (size_t)t0 * NT;
    const int*   mk   = mask + b * SEQ + t0;

    for (int idx = tid; idx < n * NT; idx += 128) {
        int t = idx / NT, j = idx - t * NT;
        float ev = em_q[idx];
        sEm[t * EMP + j] = ev;
        sEx[t * EMP + j] = fast_ex2(ev * L2E);
    }
    for (int idx = tid; idx < n; idx += 128) sMk[idx] = mk[idx];
    if (tid < 81) {
        float tv = trans[tid];
        sTr[tid] = tv;
        int k = tid / 9, j = tid - k * 9;
        sE2[k * 12 + j] = fast_ex2(tv * L2E);
    }
    __syncthreads();                 // staging + s_any=0 visible

    // tags dtype detection on this quarter's own tags
    {
        int nz = 0;
        for (int idx = tid; idx < n; idx += 128)
            nz |= (tags_words[2 * (b * SEQ + t0 + idx) + 1] != 0u);
        if (nz) atomicOr(&s_any, 1);
    }
    __syncthreads();
    const int is64 = (s_any == 0);

    // ---- chunk scans: 72 threads = 8 chunks x 16 steps, linear domain ----
    if (tid < CPB * NT) {
        const int c = tid / NT;
        const int i = tid - c * NT;

        float u[9];
        float corr = 0.0f;
        bool started = false;

        const int s0 = c * CHUNK_LEN;
        const int s1 = min(n, s0 + CHUNK_LEN);

        for (int s = s0; s < s1; ++s) {
            const int m = sMk[s];
            float4 x0 = *(const float4*)&sEx[s * EMP];
            float4 x4 = *(const float4*)&sEx[s * EMP + 4];
            float  x8 = sEx[s * EMP + 8];
            float ex[9] = {x0.x, x0.y, x0.z, x0.w, x4.x, x4.y, x4.z, x4.w, x8};
            if (m) {
                if (!started) {
#pragma unroll
                    for (int j = 0; j < 9; j++) u[j] = sE2[i * 12 + j] * ex[j];
                    started = true;
                } else {
                    float acc[9];
#pragma unroll
                    for (int j = 0; j < 9; j++) acc[j] = 0.0f;
#pragma unroll
                    for (int k = 0; k < 9; k++) {
                        float4 b0 = *(const float4*)&sE2[k * 12];
                        float4 b4 = *(const float4*)&sE2[k * 12 + 4];
                        float  b8 = sE2[k * 12 + 8];
                        acc[0] = fmaf(u[k], b0.x, acc[0]);
                        acc[1] = fmaf(u[k], b0.y, acc[1]);
                        acc[2] = fmaf(u[k], b0.z, acc[2]);
                        acc[3] = fmaf(u[k], b0.w, acc[3]);
                        acc[4] = fmaf(u[k], b4.x, acc[4]);
                        acc[5] = fmaf(u[k], b4.y, acc[5]);
                        acc[6] = fmaf(u[k], b4.z, acc[6]);
                        acc[7] = fmaf(u[k], b4.w, acc[7]);
                        acc[8] = fmaf(u[k], b8,   acc[8]);
                    }
#pragma unroll
                    for (int j = 0; j < 9; j++) u[j] = acc[j] * ex[j];
                }
            }
            if (s == s0 + 7 && started) {      // mid-chunk underflow guard
                float mxu = u[0];
#pragma unroll
                for (int j = 1; j < 9; j++) mxu = fmaxf(mxu, u[j]);
                if (mxu < 1e-10f) {
#pragma unroll
                    for (int j = 0; j < 9; j++) u[j] *= 1e10f;
                    corr -= 23.025850930f;     // ln(1e10)
                }
            }
        }
#pragma unroll
        for (int j = 0; j < 9; j++)
            sMt[c * 84 + i * 9 + j] = started
                ? (fmaf(fast_lg2(u[j]), LN2, corr))
                : ((i == j) ? 0.0f : -1e30f);
    }

    // ---- numerator contribution for this quarter ----
    {
        const long long* t64 = (const long long*)tags_words;
        const int*       t32 = (const int*)tags_words;
        const int lane = tid & 31;

        float acc = 0.0f;
        int   msum = 0;
        for (int idx = tid; idx < n; idx += 128) {
            const int s = t0 + idx;            // global position >= 1
            const int m = sMk[idx];
            msum += m;
            int tp  = is64 ? (int)t64[b * SEQ + s - 1] : t32[b * SEQ + s - 1];
            int tcu = is64 ? (int)t64[b * SEQ + s]     : t32[b * SEQ + s];
            acc += (float)m * (sTr[tp * 9 + tcu] + sEm[idx * EMP + tcu]);
        }
        if (qq == 0 && tid == 0) msum += mask[b * SEQ];
#pragma unroll
        for (int o = 16; o > 0; o >>= 1) {
            acc  += __shfl_down_sync(0xffffffffu, acc, o);
            msum += __shfl_down_sync(0xffffffffu, msum, o);
        }
        if (lane == 0) {
            atomicAdd(&s_accf, acc);
            atomicAdd(&s_msum, msum);
        }
    }

    // ---- tree combine: 8 -> 4 -> 2 -> 1 (log domain) ----
#pragma unroll
    for (int lvl = 0; lvl < 3; ++lvl) {
        const int np = 4 >> lvl;
        const int active = np * NT;
        __syncthreads();
        if (tid < active) {
            const int p = tid / NT, i = tid - (tid / NT) * NT;
            const float* Br = &sMt[(2 * p + 1) * 84 + i * 9];
#pragma unroll
            for (int j = 0; j < 9; j++)
                sEB[p * 112 + i * 12 + j] = fast_ex2(Br[j] * L2E);
        }
        __syncthreads();
        float C[9];
        int p = 0, i = 0;
        if (tid < active) {
            p = tid / NT; i = tid - p * NT;
            const float* Ar = &sMt[(2 * p) * 84 + i * 9];
            float a[9];
#pragma unroll
            for (int k = 0; k < 9; k++) a[k] = Ar[k];
            float r = a[0];
#pragma unroll
            for (int k = 1; k < 9; k++) r = fmaxf(r, a[k]);
            float e[9];
#pragma unroll
            for (int k = 0; k < 9; k++) e[k] = fast_ex2((a[k] - r) * L2E);
            float acc[9];
#pragma unroll
            for (int j = 0; j < 9; j++) acc[j] = 0.0f;
#pragma unroll
            for (int k = 0; k < 9; k++) {
                float4 b0 = *(const float4*)&sEB[p * 112 + k * 12];
                float4 b4 = *(const float4*)&sEB[p * 112 + k * 12 + 4];
                float  b8 = sEB[p * 112 + k * 12 + 8];
                acc[0] = fmaf(e[k], b0.x, acc[0]);
                acc[1] = fmaf(e[k], b0.y, acc[1]);
                acc[2] = fmaf(e[k], b0.z, acc[2]);
                acc[3] = fmaf(e[k], b0.w, acc[3]);
                acc[4] = fmaf(e[k], b4.x, acc[4]);
                acc[5] = fmaf(e[k], b4.y, acc[5]);
                acc[6] = fmaf(e[k], b4.z, acc[6]);
                acc[7] = fmaf(e[k], b4.w, acc[7]);
                acc[8] = fmaf(e[k], b8,   acc[8]);
            }
#pragma unroll
            for (int j = 0; j < 9; j++) C[j] = fmaf(fast_lg2(acc[j]), LN2, r);
        }
        __syncthreads();
        if (tid < active) {
#pragma unroll
            for (int j = 0; j < 9; j++) sMt[p * 84 + i * 9 + j] = C[j];
        }
    }
    __syncthreads();

    // ---- publish quarter result + batch ticket ----
    if (tid < 81) g_M[(b * NQ + qq) * 81 + tid] = sMt[tid];
    __syncthreads();
    if (tid == 0) {
        atomicAdd(&g_num[b], s_accf);
        atomicAdd(&g_cnt[b], s_msum);
        __threadfence();
        int old = atomicAdd(&g_btick[b], 1);
        s_last = (old == NQ - 1);
    }
    __syncthreads();
    if (!s_last) return;

    // ======================= finalize this batch ===========================
    if (tid < 32) {
        __threadfence();
        const long long* t64 = (const long long*)tags_words;
        const int*       t32 = (const int*)tags_words;

        const int j = tid;
        float v = (j < 9) ? (startT[j] + em_b[j]) : -1e30f;
        for (int c = 0; c < NQ; c++) {
            const float* Mc = g_M + (b * NQ + c) * 81;
            float vals[9];
#pragma unroll
            for (int i2 = 0; i2 < 9; i2++) {
                float sv = __shfl_sync(0xffffffffu, v, i2);
                vals[i2] = sv + ((j < 9) ? Mc[i2 * 9 + j] : 0.0f);
            }
            float nv = -1e30f;
            if (j < 9) {
                float mx = vals[0];
#pragma unroll
                for (int i2 = 1; i2 < 9; i2++) mx = fmaxf(mx, vals[i2]);
                float s = 0.0f;
#pragma unroll
                for (int i2 = 0; i2 < 9; i2++) s += fast_ex2((vals[i2] - mx) * L2E);
                nv = fmaf(fast_lg2(s), LN2, mx);
            }
            v = nv;
        }
        float x = (j < 9) ? v + endT[j] : -1e30f;
        float mx = x;
#pragma unroll
        for (int o = 16; o > 0; o >>= 1) mx = fmaxf(mx, __shfl_xor_sync(0xffffffffu, mx, o));
        float e = (j < 9) ? fast_ex2((x - mx) * L2E) : 0.0f;
#pragma unroll
        for (int o = 16; o > 0; o >>= 1) e += __shfl_xor_sync(0xffffffffu, e, o);
        if (tid == 0) {
            float den = fmaf(fast_lg2(e), LN2, mx);
            int tg0  = is64 ? (int)t64[b * SEQ] : t32[b * SEQ];
            int last = g_cnt[b] - 1;
            int tl   = is64 ? (int)t64[b * SEQ + last] : t32[b * SEQ + last];
            g_bll[b] = g_num[b] + startT[tg0] + em_b[tg0] + endT[tl] - den;
            // self-reset for next graph replay
            g_num[b] = 0.0f; g_cnt[b] = 0; g_btick[b] = 0;
#pragma unroll
            for (int c = 0; c < NQ; c++) g_qtick[b * NQ + c] = 0;
            __threadfence();
            int o = atomicAdd(&g_done, 1);
            s_fin = (o == BATCH - 1);
        }
    }
    __syncthreads();

    // =================== global sum (very last block only) =================
    if (s_fin && tid == 0) {
        __threadfence();
        float s = 0.0f;
#pragma unroll
        for (int i = 0; i < BATCH; i++) s += g_bll[i];
        out[0] = s;
        g_done = 0;                  // self-reset
    }
}

// ---------------------------------------------------------------------------
extern "C" void kernel_launch(void* const* d_in, const int* in_sizes, int n_in,
                              void* d_out, int out_size)
{
    const float* embed  = (const float*)d_in[0];
    const void*  tags   = d_in[1];
    const int*   mask   = (const int*)d_in[2];
    const float* W      = (const float*)d_in[3];
    const float* bias   = (const float*)d_in[4];
    const float* startT = (const float*)d_in[5];
    const float* endT   = (const float*)d_in[6];
    const float* trans  = (const float*)d_in[7];
    float* out = (float*)d_out;

    emis_crf<<<(BATCH * SEQ) / 32, 128>>>(embed, W, bias,
                                          (const unsigned*)tags, mask,
                                          startT, endT, trans, out);
}

// round 14
// speedup vs baseline: 1.6207x; 1.6207x over previous
#include <cuda_runtime.h>
#include <cstdint>

#define NT      9
#define SEQ     512
#define BATCH   64
#define EMB     1024
#define NQ      4
#define CHUNK_LEN 16
#define CPB     8
#define EMP     12

#define L2E 1.4426950408889634f
#define LN2 0.6931471805599453f

__device__ float g_M[BATCH * NQ * 81];
__device__ float g_num[BATCH];
__device__ int   g_cnt[BATCH];
__device__ int   g_ticket[BATCH];
__device__ int   g_tags64;

__device__ __forceinline__ void ffma2(unsigned long long& acc,
                                      unsigned long long a,
                                      unsigned long long b)
{
    asm("fma.rn.f32x2 %0, %1, %2, %3;" : "=l"(acc) : "l"(a), "l"(b), "l"(acc));
}
__device__ __forceinline__ unsigned long long dup2(float x)
{
    unsigned long long r; asm("mov.b64 %0, {%1,%1};" : "=l"(r) : "f"(x)); return r;
}
__device__ __forceinline__ float fast_ex2(float x)
{
    float r; asm("ex2.approx.ftz.f32 %0, %1;" : "=f"(r) : "f"(x)); return r;
}
__device__ __forceinline__ float fast_lg2(float x)
{
    float r; asm("lg2.approx.ftz.f32 %0, %1;" : "=f"(r) : "f"(x)); return r;
}
__device__ __forceinline__ void cp16(float* smem_dst, const float* gsrc)
{
    unsigned a = (unsigned)__cvta_generic_to_shared(smem_dst);
    asm volatile("cp.async.cg.shared.global [%0], [%1], 16;" :: "r"(a), "l"(gsrc));
}

// ---------------------------------------------------------------------------
// Kernel 1: emission = log_softmax(embed @ W^T + b)
// grid 1024, block 128 = 32 rows. x tiles (32x64) double-buffered via
// cp.async.cg (zero prefetch registers). Thread = (rowpair {p,p+16},
// 8-col slice s): W broadcast LDS amortized over 2 rows (24 instr/warp-tile
// vs emis6's 48). W tile register-prefetched (pw[5]) into a double smem buf.
// ---------------------------------------------------------------------------
__global__ __launch_bounds__(128) void emis11(
    const float* __restrict__ embed,
    const float* __restrict__ W,
    const float* __restrict__ bias,
    const unsigned* __restrict__ tags_words,
    float* __restrict__ out)
{
    __shared__ __align__(16) float sX[2 * 2176];   // 2 x (32 rows x 68)
    __shared__ __align__(16) float sWt[2 * 768];   // 2 x (64 x 12)

    const int tid = threadIdx.x;

    if (blockIdx.x == 0) {
        __shared__ int s_any;
        if (tid == 0) s_any = 0;
        __syncthreads();
        int nz = 0;
        for (int qq = tid; qq < 2048; qq += 128)
            nz |= (tags_words[2 * qq + 1] != 0u);
        if (nz) atomicOr(&s_any, 1);
        __syncthreads();
        if (tid == 0) {
            g_tags64 = s_any ? 0 : 1;
            out[0] = 0.0f;
        }
        if (tid < BATCH) {
            g_num[tid] = 0.0f;
            g_cnt[tid] = 0;
            g_ticket[tid] = 0;
        }
    }

    const int warp = tid >> 5;
    const int lane = tid & 31;
    const int p = lane & 15;               // rowpair: rows p, p+16
    const int s = warp * 2 + (lane >> 4);  // col slice 0..7 (8 cols/tile)
    const int rowBase = blockIdx.x * 32;
    const float* gbase = embed + (size_t)rowBase * EMB;

    // -------- prologue: async x tiles 0,1 ; W tile 0 into registers --------
    {
#pragma unroll
        for (int it = 0; it < 4; ++it) {
            int idx = it * 128 + tid;
            int r2 = idx >> 4, cc = (idx & 15) * 4;
            cp16(&sX[r2 * 68 + cc], gbase + (size_t)r2 * EMB + cc);
        }
        asm volatile("cp.async.commit_group;");
#pragma unroll
        for (int it = 0; it < 4; ++it) {
            int idx = it * 128 + tid;
            int r2 = idx >> 4, cc = (idx & 15) * 4;
            cp16(&sX[2176 + r2 * 68 + cc], gbase + 64 + (size_t)r2 * EMB + cc);
        }
        asm volatile("cp.async.commit_group;");
    }
    float pw[5];
#pragma unroll
    for (int it = 0; it < 5; ++it) {
        int idx = it * 128 + tid;
        if (idx < 576) {
            int t = idx >> 6, e = idx & 63;
            pw[it] = W[t * EMB + e];
        }
    }

    unsigned long long a01_0 = 0ull, a23_0 = 0ull, a45_0 = 0ull, a67_0 = 0ull;
    unsigned long long a01_1 = 0ull, a23_1 = 0ull, a45_1 = 0ull, a67_1 = 0ull;
    float a8_0 = 0.0f, a8_1 = 0.0f;

    for (int tile = 0; tile < 16; ++tile) {
        if (tile < 15) asm volatile("cp.async.wait_group 1;");
        else           asm volatile("cp.async.wait_group 0;");
        __syncthreads();             // x[tile] resident; W buf (tile&1) free

        // store W tile from registers into its double buffer
        float* wbuf = &sWt[(tile & 1) * 768];
#pragma unroll
        for (int it = 0; it < 5; ++it) {
            int idx = it * 128 + tid;
            if (idx < 576) {
                int t = idx >> 6, e = idx & 63;
                wbuf[e * 12 + t] = pw[it];
            }
        }
        // prefetch next W tile
        if (tile < 15) {
#pragma unroll
            for (int it = 0; it < 5; ++it) {
                int idx = it * 128 + tid;
                if (idx < 576) {
                    int t = idx >> 6, e = idx & 63;
                    pw[it] = W[t * EMB + (tile + 1) * 64 + e];
                }
            }
        }
        __syncthreads();             // W tile visible

        // compute: 8 cols (slice s) x 2 rows (p, p+16)
        const float* xb  = &sX[(tile & 1) * 2176];
        const float* xr0 = xb + p * 68 + s * 8;
        const float* xr1 = xb + (p + 16) * 68 + s * 8;
        const float* wq  = wbuf + (s * 8) * 12;
#pragma unroll
        for (int e4 = 0; e4 < 8; e4 += 4) {
            float4 xa4 = *(const float4*)(xr0 + e4);
            float4 xb4 = *(const float4*)(xr1 + e4);
#pragma unroll
            for (int u = 0; u < 4; ++u) {
                float xa = (u == 0) ? xa4.x : (u == 1) ? xa4.y : (u == 2) ? xa4.z : xa4.w;
                float xv = (u == 0) ? xb4.x : (u == 1) ? xb4.y : (u == 2) ? xb4.z : xb4.w;
                const float* we = wq + (e4 + u) * 12;
                ulonglong2 wA = *(const ulonglong2*)we;        // {w0,w1},{w2,w3}
                ulonglong2 wB = *(const ulonglong2*)(we + 4);  // {w4,w5},{w6,w7}
                float w8 = we[8];
                unsigned long long da = dup2(xa);
                unsigned long long db = dup2(xv);
                ffma2(a01_0, da, wA.x); ffma2(a23_0, da, wA.y);
                ffma2(a45_0, da, wB.x); ffma2(a67_0, da, wB.y);
                a8_0 = fmaf(xa, w8, a8_0);
                ffma2(a01_1, db, wA.x); ffma2(a23_1, db, wA.y);
                ffma2(a45_1, db, wB.x); ffma2(a67_1, db, wB.y);
                a8_1 = fmaf(xv, w8, a8_1);
            }
        }
        __syncthreads();             // done reading x buffer (tile&1)

        if (tile + 2 < 16) {
            float* nbuf = &sX[(tile & 1) * 2176];
            const float* g = gbase + (tile + 2) * 64;
#pragma unroll
            for (int it = 0; it < 4; ++it) {
                int idx = it * 128 + tid;
                int r2 = idx >> 4, cc = (idx & 15) * 4;
                cp16(nbuf + r2 * 68 + cc, g + (size_t)r2 * EMB + cc);
            }
            asm volatile("cp.async.commit_group;");
        }
    }

    // -------- reduction across slices + log_softmax --------
    float* red = sX;                  // red[row][73], 2336 floats (fits 4352)
    {
        float2 f;
        float* r0 = &red[p * 73 + s * 9];
        f = *(float2*)&a01_0; r0[0] = f.x; r0[1] = f.y;
        f = *(float2*)&a23_0; r0[2] = f.x; r0[3] = f.y;
        f = *(float2*)&a45_0; r0[4] = f.x; r0[5] = f.y;
        f = *(float2*)&a67_0; r0[6] = f.x; r0[7] = f.y;
        r0[8] = a8_0;
        float* r1 = &red[(p + 16) * 73 + s * 9];
        f = *(float2*)&a01_1; r1[0] = f.x; r1[1] = f.y;
        f = *(float2*)&a23_1; r1[2] = f.x; r1[3] = f.y;
        f = *(float2*)&a45_1; r1[4] = f.x; r1[5] = f.y;
        f = *(float2*)&a67_1; r1[6] = f.x; r1[7] = f.y;
        r1[8] = a8_1;
    }
    __syncthreads();

    if (tid < 32) {
        const float* rp = &red[tid * 73];
        float acc[NT];
#pragma unroll
        for (int t = 0; t < NT; t++) {
            float sum = bias[t];
#pragma unroll
            for (int qq = 0; qq < 8; qq++) sum += rp[qq * 9 + t];
            acc[t] = sum;
        }

        float mx = acc[0];
#pragma unroll
        for (int t = 1; t < NT; t++) mx = fmaxf(mx, acc[t]);
        float sum = 0.0f;
#pragma unroll
        for (int t = 0; t < NT; t++) sum += fast_ex2((acc[t] - mx) * L2E);
        float lse = fmaf(fast_lg2(sum), LN2, mx);

        float* o = out + 1 + (size_t)(rowBase + tid) * NT;
#pragma unroll
        for (int t = 0; t < NT; t++) o[t] = acc[t] - lse;
    }
}

// ---------------------------------------------------------------------------
// Kernel 2 (R12, proven): CRF scan + fused finalize, linear-domain scan.
// ---------------------------------------------------------------------------
__global__ __launch_bounds__(96) void crf_scan_fin(
    float* __restrict__ outbuf,
    const void* __restrict__ tags,
    const int*  __restrict__ mask,
    const float* __restrict__ startT,
    const float* __restrict__ endT,
    const float* __restrict__ trans)
{
    const float* emis = outbuf + 1;
    const int q = blockIdx.x, b = blockIdx.y;
    const int tid = threadIdx.x;
    const int lane = tid & 31;

    __shared__ __align__(16) float sEm[128 * EMP];
    __shared__ __align__(16) float sEx[128 * EMP];
    __shared__ int   sMk[128];
    __shared__ float sTr[84];
    __shared__ __align__(16) float sE2[112];
    __shared__ __align__(16) float sMt[CPB][84];
    __shared__ __align__(16) float sEB[4][112];
    __shared__ float s_accf;
    __shared__ int   s_msum;
    __shared__ int   s_last;

    const int t0_blk = 1 + q * 128;
    const int n = min(SEQ - t0_blk, 128);

    const float* em_b = emis + (size_t)b * SEQ * NT;
    const float* em_q = em_b + (size_t)t0_blk * NT;
    const int*   mk   = mask + b * SEQ + t0_blk;

    if (tid == 0) { s_accf = 0.0f; s_msum = 0; }
    for (int idx = tid; idx < n * NT; idx += 96) {
        int t = idx / NT, j = idx - t * NT;
        float ev = em_q[idx];
        sEm[t * EMP + j] = ev;
        sEx[t * EMP + j] = fast_ex2(ev * L2E);
    }
    for (int idx = tid; idx < n; idx += 96) sMk[idx] = mk[idx];
    if (tid < 81) {
        float tv = trans[tid];
        sTr[tid] = tv;
        int k = tid / 9, j = tid - k * 9;
        sE2[k * 12 + j] = fast_ex2(tv * L2E);
    }
    __syncthreads();

    if (tid < CPB * NT) {
        const int c = tid / NT;
        const int i = tid - c * NT;

        float u[9];
        float corr = 0.0f;
        bool started = false;

        const int s0 = c * CHUNK_LEN;
        const int s1 = min(n, s0 + CHUNK_LEN);

        for (int s = s0; s < s1; ++s) {
            const int m = sMk[s];
            float4 x0 = *(const float4*)&sEx[s * EMP];
            float4 x4 = *(const float4*)&sEx[s * EMP + 4];
            float  x8 = sEx[s * EMP + 8];
            float ex[9] = {x0.x, x0.y, x0.z, x0.w, x4.x, x4.y, x4.z, x4.w, x8};
            if (m) {
                if (!started) {
#pragma unroll
                    for (int j = 0; j < 9; j++) u[j] = sE2[i * 12 + j] * ex[j];
                    started = true;
                } else {
                    float acc[9];
#pragma unroll
                    for (int j = 0; j < 9; j++) acc[j] = 0.0f;
#pragma unroll
                    for (int k = 0; k < 9; k++) {
                        float4 b0 = *(const float4*)&sE2[k * 12];
                        float4 b4 = *(const float4*)&sE2[k * 12 + 4];
                        float  b8 = sE2[k * 12 + 8];
                        acc[0] = fmaf(u[k], b0.x, acc[0]);
                        acc[1] = fmaf(u[k], b0.y, acc[1]);
                        acc[2] = fmaf(u[k], b0.z, acc[2]);
                        acc[3] = fmaf(u[k], b0.w, acc[3]);
                        acc[4] = fmaf(u[k], b4.x, acc[4]);
                        acc[5] = fmaf(u[k], b4.y, acc[5]);
                        acc[6] = fmaf(u[k], b4.z, acc[6]);
                        acc[7] = fmaf(u[k], b4.w, acc[7]);
                        acc[8] = fmaf(u[k], b8,   acc[8]);
                    }
#pragma unroll
                    for (int j = 0; j < 9; j++) u[j] = acc[j] * ex[j];
                }
            }
            if (s == s0 + 7 && started) {
                float mxu = u[0];
#pragma unroll
                for (int j = 1; j < 9; j++) mxu = fmaxf(mxu, u[j]);
                if (mxu < 1e-10f) {
#pragma unroll
                    for (int j = 0; j < 9; j++) u[j] *= 1e10f;
                    corr -= 23.025850930f;
                }
            }
        }
#pragma unroll
        for (int j = 0; j < 9; j++)
            sMt[c][i * 9 + j] = started
                ? (fmaf(fast_lg2(u[j]), LN2, corr))
                : ((i == j) ? 0.0f : -1e30f);
    }

    {
        const long long* t64 = (const long long*)tags;
        const int*       t32 = (const int*)tags;
        const int is64 = g_tags64;

        float acc = 0.0f;
        int   msum = 0;
        for (int idx = tid; idx < n; idx += 96) {
            const int s = t0_blk + idx;
            const int m = sMk[idx];
            msum += m;
            int tp  = is64 ? (int)t64[b * SEQ + s - 1] : t32[b * SEQ + s - 1];
            int tcu = is64 ? (int)t64[b * SEQ + s]     : t32[b * SEQ + s];
            acc += (float)m * (sTr[tp * 9 + tcu] + sEm[idx * EMP + tcu]);
        }
        if (q == 0 && tid == 0) msum += mask[b * SEQ];
#pragma unroll
        for (int o = 16; o > 0; o >>= 1) {
            acc  += __shfl_down_sync(0xffffffffu, acc, o);
            msum += __shfl_down_sync(0xffffffffu, msum, o);
        }
        if (lane == 0) {
            atomicAdd(&s_accf, acc);
            atomicAdd(&s_msum, msum);
        }
    }

#pragma unroll
    for (int lvl = 0; lvl < 3; ++lvl) {
        const int np = 4 >> lvl;
        const int active = np * NT;
        __syncthreads();
        if (tid < active) {
            const int pp = tid / NT, i = tid - (tid / NT) * NT;
            const float* Br = &sMt[2 * pp + 1][i * 9];
#pragma unroll
            for (int j = 0; j < 9; j++)
                sEB[pp][i * 12 + j] = fast_ex2(Br[j] * L2E);
        }
        __syncthreads();
        float C[9];
        int pp = 0, i = 0;
        if (tid < active) {
            pp = tid / NT; i = tid - pp * NT;
            const float* Ar = &sMt[2 * pp][i * 9];
            float a[9];
#pragma unroll
            for (int k = 0; k < 9; k++) a[k] = Ar[k];
            float r = a[0];
#pragma unroll
            for (int k = 1; k < 9; k++) r = fmaxf(r, a[k]);
            float e[9];
#pragma unroll
            for (int k = 0; k < 9; k++) e[k] = fast_ex2((a[k] - r) * L2E);
            float acc[9];
#pragma unroll
            for (int j = 0; j < 9; j++) acc[j] = 0.0f;
#pragma unroll
            for (int k = 0; k < 9; k++) {
                float4 b0 = *(const float4*)&sEB[pp][k * 12];
                float4 b4 = *(const float4*)&sEB[pp][k * 12 + 4];
                float  b8 = sEB[pp][k * 12 + 8];
                acc[0] = fmaf(e[k], b0.x, acc[0]);
                acc[1] = fmaf(e[k], b0.y, acc[1]);
                acc[2] = fmaf(e[k], b0.z, acc[2]);
                acc[3] = fmaf(e[k], b0.w, acc[3]);
                acc[4] = fmaf(e[k], b4.x, acc[4]);
                acc[5] = fmaf(e[k], b4.y, acc[5]);
                acc[6] = fmaf(e[k], b4.z, acc[6]);
                acc[7] = fmaf(e[k], b4.w, acc[7]);
                acc[8] = fmaf(e[k], b8,   acc[8]);
            }
#pragma unroll
            for (int j = 0; j < 9; j++) C[j] = fmaf(fast_lg2(acc[j]), LN2, r);
        }
        __syncthreads();
        if (tid < active) {
#pragma unroll
            for (int j = 0; j < 9; j++) sMt[pp][i * 9 + j] = C[j];
        }
    }
    __syncthreads();

    if (tid < 81) g_M[(b * NQ + q) * 81 + tid] = sMt[0][tid];
    if (tid == 0) {
        atomicAdd(&g_num[b], s_accf);
        atomicAdd(&g_cnt[b], s_msum);
        __threadfence();
        int old = atomicAdd(&g_ticket[b], 1);
        s_last = (old == NQ - 1);
    }
    __syncthreads();

    if (s_last && tid < 32) {
        __threadfence();
        const long long* t64 = (const long long*)tags;
        const int*       t32 = (const int*)tags;
        const int is64 = g_tags64;

        const int j = tid;
        float v = (j < 9) ? (startT[j] + em_b[j]) : -1e30f;
        for (int c = 0; c < NQ; c++) {
            const float* Mc = g_M + (b * NQ + c) * 81;
            float vals[9];
#pragma unroll
            for (int i2 = 0; i2 < 9; i2++) {
                float sv = __shfl_sync(0xffffffffu, v, i2);
                vals[i2] = sv + ((j < 9) ? Mc[i2 * 9 + j] : 0.0f);
            }
            float nv = -1e30f;
            if (j < 9) {
                float mx = vals[0];
#pragma unroll
                for (int i2 = 1; i2 < 9; i2++) mx = fmaxf(mx, vals[i2]);
                float s = 0.0f;
#pragma unroll
                for (int i2 = 0; i2 < 9; i2++) s += fast_ex2((vals[i2] - mx) * L2E);
                nv = fmaf(fast_lg2(s), LN2, mx);
            }
            v = nv;
        }
        float x = (j < 9) ? v + endT[j] : -1e30f;
        float mx = x;
#pragma unroll
        for (int o = 16; o > 0; o >>= 1) mx = fmaxf(mx, __shfl_xor_sync(0xffffffffu, mx, o));
        float e = (j < 9) ? fast_ex2((x - mx) * L2E) : 0.0f;
#pragma unroll
        for (int o = 16; o > 0; o >>= 1) e += __shfl_xor_sync(0xffffffffu, e, o);
        if (tid == 0) {
            float den = fmaf(fast_lg2(e), LN2, mx);
            int tg0  = is64 ? (int)t64[b * SEQ] : t32[b * SEQ];
            int last = g_cnt[b] - 1;
            int tl   = is64 ? (int)t64[b * SEQ + last] : t32[b * SEQ + last];
            float num = g_num[b] + startT[tg0] + em_b[tg0] + endT[tl];
            atomicAdd(outbuf, num - den);
        }
    }
}

// ---------------------------------------------------------------------------
extern "C" void kernel_launch(void* const* d_in, const int* in_sizes, int n_in,
                              void* d_out, int out_size)
{
    const float* embed  = (const float*)d_in[0];
    const void*  tags   = d_in[1];
    const int*   mask   = (const int*)d_in[2];
    const float* W      = (const float*)d_in[3];
    const float* bias   = (const float*)d_in[4];
    const float* startT = (const float*)d_in[5];
    const float* endT   = (const float*)d_in[6];
    const float* trans  = (const float*)d_in[7];
    float* out = (float*)d_out;

    emis11<<<(BATCH * SEQ) / 32, 128>>>(embed, W, bias,
                                        (const unsigned*)tags, out);
    dim3 g2(NQ, BATCH);
    crf_scan_fin<<<g2, 96>>>(out, tags, mask, startT, endT, trans);
}

// round 15
// speedup vs baseline: 1.6350x; 1.0088x over previous
#include <cuda_runtime.h>
#include <cstdint>

#define NT      9
#define SEQ     512
#define BATCH   64
#define EMB     1024
#define NQ      4
#define CHUNK_LEN 8
#define CPB     16
#define EMP     12
#define STH     160             // scan kernel block size

#define L2E 1.4426950408889634f
#define LN2 0.6931471805599453f

__device__ float g_M[BATCH * NQ * 81];
__device__ float g_num[BATCH];
__device__ int   g_cnt[BATCH];
__device__ int   g_ticket[BATCH];
__device__ int   g_tags64;

__device__ __forceinline__ void ffma2(unsigned long long& acc,
                                      unsigned long long a,
                                      unsigned long long b)
{
    asm("fma.rn.f32x2 %0, %1, %2, %3;" : "=l"(acc) : "l"(a), "l"(b), "l"(acc));
}
__device__ __forceinline__ unsigned long long dup2(float x)
{
    unsigned long long r; asm("mov.b64 %0, {%1,%1};" : "=l"(r) : "f"(x)); return r;
}
__device__ __forceinline__ float fast_ex2(float x)
{
    float r; asm("ex2.approx.ftz.f32 %0, %1;" : "=f"(r) : "f"(x)); return r;
}
__device__ __forceinline__ float fast_lg2(float x)
{
    float r; asm("lg2.approx.ftz.f32 %0, %1;" : "=f"(r) : "f"(x)); return r;
}
__device__ __forceinline__ void cp16(float* smem_dst, const float* gsrc)
{
    unsigned a = (unsigned)__cvta_generic_to_shared(smem_dst);
    asm volatile("cp.async.cg.shared.global [%0], [%1], 16;" :: "r"(a), "l"(gsrc));
}

// ---------------------------------------------------------------------------
// Kernel 1 (PROVEN emis11, R14): emission = log_softmax(embed @ W^T + b)
// grid 1024, block 128 = 32 rows. x tiles double-buffered via cp.async.cg;
// thread = (rowpair {p,p+16}, 8-col slice): W LDS amortized over 2 rows.
// ---------------------------------------------------------------------------
__global__ __launch_bounds__(128) void emis11(
    const float* __restrict__ embed,
    const float* __restrict__ W,
    const float* __restrict__ bias,
    const unsigned* __restrict__ tags_words,
    float* __restrict__ out)
{
    __shared__ __align__(16) float sX[2 * 2176];   // 2 x (32 rows x 68)
    __shared__ __align__(16) float sWt[2 * 768];   // 2 x (64 x 12)

    const int tid = threadIdx.x;

    if (blockIdx.x == 0) {
        __shared__ int s_any;
        if (tid == 0) s_any = 0;
        __syncthreads();
        int nz = 0;
        for (int qq = tid; qq < 2048; qq += 128)
            nz |= (tags_words[2 * qq + 1] != 0u);
        if (nz) atomicOr(&s_any, 1);
        __syncthreads();
        if (tid == 0) {
            g_tags64 = s_any ? 0 : 1;
            out[0] = 0.0f;
        }
        if (tid < BATCH) {
            g_num[tid] = 0.0f;
            g_cnt[tid] = 0;
            g_ticket[tid] = 0;
        }
    }

    const int warp = tid >> 5;
    const int lane = tid & 31;
    const int p = lane & 15;
    const int s = warp * 2 + (lane >> 4);
    const int rowBase = blockIdx.x * 32;
    const float* gbase = embed + (size_t)rowBase * EMB;

    {
#pragma unroll
        for (int it = 0; it < 4; ++it) {
            int idx = it * 128 + tid;
            int r2 = idx >> 4, cc = (idx & 15) * 4;
            cp16(&sX[r2 * 68 + cc], gbase + (size_t)r2 * EMB + cc);
        }
        asm volatile("cp.async.commit_group;");
#pragma unroll
        for (int it = 0; it < 4; ++it) {
            int idx = it * 128 + tid;
            int r2 = idx >> 4, cc = (idx & 15) * 4;
            cp16(&sX[2176 + r2 * 68 + cc], gbase + 64 + (size_t)r2 * EMB + cc);
        }
        asm volatile("cp.async.commit_group;");
    }
    float pw[5];
#pragma unroll
    for (int it = 0; it < 5; ++it) {
        int idx = it * 128 + tid;
        if (idx < 576) {
            int t = idx >> 6, e = idx & 63;
            pw[it] = W[t * EMB + e];
        }
    }

    unsigned long long a01_0 = 0ull, a23_0 = 0ull, a45_0 = 0ull, a67_0 = 0ull;
    unsigned long long a01_1 = 0ull, a23_1 = 0ull, a45_1 = 0ull, a67_1 = 0ull;
    float a8_0 = 0.0f, a8_1 = 0.0f;

    for (int tile = 0; tile < 16; ++tile) {
        if (tile < 15) asm volatile("cp.async.wait_group 1;");
        else           asm volatile("cp.async.wait_group 0;");
        __syncthreads();

        float* wbuf = &sWt[(tile & 1) * 768];
#pragma unroll
        for (int it = 0; it < 5; ++it) {
            int idx = it * 128 + tid;
            if (idx < 576) {
                int t = idx >> 6, e = idx & 63;
                wbuf[e * 12 + t] = pw[it];
            }
        }
        if (tile < 15) {
#pragma unroll
            for (int it = 0; it < 5; ++it) {
                int idx = it * 128 + tid;
                if (idx < 576) {
                    int t = idx >> 6, e = idx & 63;
                    pw[it] = W[t * EMB + (tile + 1) * 64 + e];
                }
            }
        }
        __syncthreads();

        const float* xb  = &sX[(tile & 1) * 2176];
        const float* xr0 = xb + p * 68 + s * 8;
        const float* xr1 = xb + (p + 16) * 68 + s * 8;
        const float* wq  = wbuf + (s * 8) * 12;
#pragma unroll
        for (int e4 = 0; e4 < 8; e4 += 4) {
            float4 xa4 = *(const float4*)(xr0 + e4);
            float4 xb4 = *(const float4*)(xr1 + e4);
#pragma unroll
            for (int u = 0; u < 4; ++u) {
                float xa = (u == 0) ? xa4.x : (u == 1) ? xa4.y : (u == 2) ? xa4.z : xa4.w;
                float xv = (u == 0) ? xb4.x : (u == 1) ? xb4.y : (u == 2) ? xb4.z : xb4.w;
                const float* we = wq + (e4 + u) * 12;
                ulonglong2 wA = *(const ulonglong2*)we;
                ulonglong2 wB = *(const ulonglong2*)(we + 4);
                float w8 = we[8];
                unsigned long long da = dup2(xa);
                unsigned long long db = dup2(xv);
                ffma2(a01_0, da, wA.x); ffma2(a23_0, da, wA.y);
                ffma2(a45_0, da, wB.x); ffma2(a67_0, da, wB.y);
                a8_0 = fmaf(xa, w8, a8_0);
                ffma2(a01_1, db, wA.x); ffma2(a23_1, db, wA.y);
                ffma2(a45_1, db, wB.x); ffma2(a67_1, db, wB.y);
                a8_1 = fmaf(xv, w8, a8_1);
            }
        }
        __syncthreads();

        if (tile + 2 < 16) {
            float* nbuf = &sX[(tile & 1) * 2176];
            const float* g = gbase + (tile + 2) * 64;
#pragma unroll
            for (int it = 0; it < 4; ++it) {
                int idx = it * 128 + tid;
                int r2 = idx >> 4, cc = (idx & 15) * 4;
                cp16(nbuf + r2 * 68 + cc, g + (size_t)r2 * EMB + cc);
            }
            asm volatile("cp.async.commit_group;");
        }
    }

    float* red = sX;
    {
        float2 f;
        float* r0 = &red[p * 73 + s * 9];
        f = *(float2*)&a01_0; r0[0] = f.x; r0[1] = f.y;
        f = *(float2*)&a23_0; r0[2] = f.x; r0[3] = f.y;
        f = *(float2*)&a45_0; r0[4] = f.x; r0[5] = f.y;
        f = *(float2*)&a67_0; r0[6] = f.x; r0[7] = f.y;
        r0[8] = a8_0;
        float* r1 = &red[(p + 16) * 73 + s * 9];
        f = *(float2*)&a01_1; r1[0] = f.x; r1[1] = f.y;
        f = *(float2*)&a23_1; r1[2] = f.x; r1[3] = f.y;
        f = *(float2*)&a45_1; r1[4] = f.x; r1[5] = f.y;
        f = *(float2*)&a67_1; r1[6] = f.x; r1[7] = f.y;
        r1[8] = a8_1;
    }
    __syncthreads();

    if (tid < 32) {
        const float* rp = &red[tid * 73];
        float acc[NT];
#pragma unroll
        for (int t = 0; t < NT; t++) {
            float sum = bias[t];
#pragma unroll
            for (int qq = 0; qq < 8; qq++) sum += rp[qq * 9 + t];
            acc[t] = sum;
        }

        float mx = acc[0];
#pragma unroll
        for (int t = 1; t < NT; t++) mx = fmaxf(mx, acc[t]);
        float sum = 0.0f;
#pragma unroll
        for (int t = 0; t < NT; t++) sum += fast_ex2((acc[t] - mx) * L2E);
        float lse = fmaf(fast_lg2(sum), LN2, mx);

        float* o = out + 1 + (size_t)(rowBase + tid) * NT;
#pragma unroll
        for (int t = 0; t < NT; t++) o[t] = acc[t] - lse;
    }
}

// ---------------------------------------------------------------------------
// Kernel 2: CRF scan + fused finalize, linear-domain scan.
// R15: 160 threads (5 warps), 16 chunks x 8 steps (serial chain halved),
// float4 emission staging, 4-level tree combine (16->8->4->2->1).
// ---------------------------------------------------------------------------
__global__ __launch_bounds__(STH) void crf_scan_fin(
    float* __restrict__ outbuf,
    const void* __restrict__ tags,
    const int*  __restrict__ mask,
    const float* __restrict__ startT,
    const float* __restrict__ endT,
    const float* __restrict__ trans)
{
    const float* emis = outbuf + 1;
    const int q = blockIdx.x, b = blockIdx.y;
    const int tid = threadIdx.x;
    const int lane = tid & 31;

    __shared__ __align__(16) float sEm[128 * EMP];
    __shared__ __align__(16) float sEx[128 * EMP];
    __shared__ int   sMk[128];
    __shared__ float sTr[84];
    __shared__ __align__(16) float sE2[112];
    __shared__ __align__(16) float sMt[CPB][84];
    __shared__ __align__(16) float sEB[8][112];
    __shared__ float s_accf;
    __shared__ int   s_msum;
    __shared__ int   s_last;

    const int t0_blk = 1 + q * 128;
    const int n = min(SEQ - t0_blk, 128);

    const float* em_b = emis + (size_t)b * SEQ * NT;
    const float* em_q = em_b + (size_t)t0_blk * NT;
    const int*   mk   = mask + b * SEQ + t0_blk;

    if (tid == 0) { s_accf = 0.0f; s_msum = 0; }
    // float4 emission staging + ex2 transform
    {
        const int tot = n * NT;                    // 1152 or 1143
        const int g4  = (tot + 3) >> 2;            // float4 count
        for (int g = tid; g < g4; g += STH) {
            float4 v = *(const float4*)(em_q + g * 4);
#pragma unroll
            for (int u = 0; u < 4; ++u) {
                int idx = g * 4 + u;
                if (idx < tot) {
                    float ev = (u == 0) ? v.x : (u == 1) ? v.y : (u == 2) ? v.z : v.w;
                    int t = idx / NT, j = idx - t * NT;
                    sEm[t * EMP + j] = ev;
                    sEx[t * EMP + j] = fast_ex2(ev * L2E);
                }
            }
        }
    }
    for (int idx = tid; idx < n; idx += STH) sMk[idx] = mk[idx];
    if (tid < 81) {
        float tv = trans[tid];
        sTr[tid] = tv;
        int k = tid / 9, j = tid - k * 9;
        sE2[k * 12 + j] = fast_ex2(tv * L2E);
    }
    __syncthreads();

    // ---- chunk scans: 144 threads = 16 chunks x 9 rows, linear domain ----
    if (tid < CPB * NT) {
        const int c = tid / NT;
        const int i = tid - c * NT;

        float u[9];
        float corr = 0.0f;
        bool started = false;

        const int s0 = c * CHUNK_LEN;
        const int s1 = min(n, s0 + CHUNK_LEN);

        for (int s = s0; s < s1; ++s) {
            const int m = sMk[s];
            float4 x0 = *(const float4*)&sEx[s * EMP];
            float4 x4 = *(const float4*)&sEx[s * EMP + 4];
            float  x8 = sEx[s * EMP + 8];
            float ex[9] = {x0.x, x0.y, x0.z, x0.w, x4.x, x4.y, x4.z, x4.w, x8};
            if (m) {
                if (!started) {
#pragma unroll
                    for (int j = 0; j < 9; j++) u[j] = sE2[i * 12 + j] * ex[j];
                    started = true;
                } else {
                    float acc[9];
#pragma unroll
                    for (int j = 0; j < 9; j++) acc[j] = 0.0f;
#pragma unroll
                    for (int k = 0; k < 9; k++) {
                        float4 b0 = *(const float4*)&sE2[k * 12];
                        float4 b4 = *(const float4*)&sE2[k * 12 + 4];
                        float  b8 = sE2[k * 12 + 8];
                        acc[0] = fmaf(u[k], b0.x, acc[0]);
                        acc[1] = fmaf(u[k], b0.y, acc[1]);
                        acc[2] = fmaf(u[k], b0.z, acc[2]);
                        acc[3] = fmaf(u[k], b0.w, acc[3]);
                        acc[4] = fmaf(u[k], b4.x, acc[4]);
                        acc[5] = fmaf(u[k], b4.y, acc[5]);
                        acc[6] = fmaf(u[k], b4.z, acc[6]);
                        acc[7] = fmaf(u[k], b4.w, acc[7]);
                        acc[8] = fmaf(u[k], b8,   acc[8]);
                    }
#pragma unroll
                    for (int j = 0; j < 9; j++) u[j] = acc[j] * ex[j];
                }
            }
            if (s == s0 + 4 && started) {          // underflow guard
                float mxu = u[0];
#pragma unroll
                for (int j = 1; j < 9; j++) mxu = fmaxf(mxu, u[j]);
                if (mxu < 1e-10f) {
#pragma unroll
                    for (int j = 0; j < 9; j++) u[j] *= 1e10f;
                    corr -= 23.025850930f;
                }
            }
        }
#pragma unroll
        for (int j = 0; j < 9; j++)
            sMt[c][i * 9 + j] = started
                ? (fmaf(fast_lg2(u[j]), LN2, corr))
                : ((i == j) ? 0.0f : -1e30f);
    }

    // ---- numerator contribution for this quarter ----
    {
        const long long* t64 = (const long long*)tags;
        const int*       t32 = (const int*)tags;
        const int is64 = g_tags64;

        float acc = 0.0f;
        int   msum = 0;
        for (int idx = tid; idx < n; idx += STH) {
            const int s = t0_blk + idx;
            const int m = sMk[idx];
            msum += m;
            int tp  = is64 ? (int)t64[b * SEQ + s - 1] : t32[b * SEQ + s - 1];
            int tcu = is64 ? (int)t64[b * SEQ + s]     : t32[b * SEQ + s];
            acc += (float)m * (sTr[tp * 9 + tcu] + sEm[idx * EMP + tcu]);
        }
        if (q == 0 && tid == 0) msum += mask[b * SEQ];
#pragma unroll
        for (int o = 16; o > 0; o >>= 1) {
            acc  += __shfl_down_sync(0xffffffffu, acc, o);
            msum += __shfl_down_sync(0xffffffffu, msum, o);
        }
        if (lane == 0) {
            atomicAdd(&s_accf, acc);
            atomicAdd(&s_msum, msum);
        }
    }

    // ---- tree combine: 16 -> 8 -> 4 -> 2 -> 1 (log domain) ----
#pragma unroll
    for (int lvl = 0; lvl < 4; ++lvl) {
        const int np = 8 >> lvl;
        const int active = np * NT;
        __syncthreads();
        if (tid < active) {
            const int pp = tid / NT, i = tid - (tid / NT) * NT;
            const float* Br = &sMt[2 * pp + 1][i * 9];
#pragma unroll
            for (int j = 0; j < 9; j++)
                sEB[pp][i * 12 + j] = fast_ex2(Br[j] * L2E);
        }
        __syncthreads();
        float C[9];
        int pp = 0, i = 0;
        if (tid < active) {
            pp = tid / NT; i = tid - pp * NT;
            const float* Ar = &sMt[2 * pp][i * 9];
            float a[9];
#pragma unroll
            for (int k = 0; k < 9; k++) a[k] = Ar[k];
            float r = a[0];
#pragma unroll
            for (int k = 1; k < 9; k++) r = fmaxf(r, a[k]);
            float e[9];
#pragma unroll
            for (int k = 0; k < 9; k++) e[k] = fast_ex2((a[k] - r) * L2E);
            float acc[9];
#pragma unroll
            for (int j = 0; j < 9; j++) acc[j] = 0.0f;
#pragma unroll
            for (int k = 0; k < 9; k++) {
                float4 b0 = *(const float4*)&sEB[pp][k * 12];
                float4 b4 = *(const float4*)&sEB[pp][k * 12 + 4];
                float  b8 = sEB[pp][k * 12 + 8];
                acc[0] = fmaf(e[k], b0.x, acc[0]);
                acc[1] = fmaf(e[k], b0.y, acc[1]);
                acc[2] = fmaf(e[k], b0.z, acc[2]);
                acc[3] = fmaf(e[k], b0.w, acc[3]);
                acc[4] = fmaf(e[k], b4.x, acc[4]);
                acc[5] = fmaf(e[k], b4.y, acc[5]);
                acc[6] = fmaf(e[k], b4.z, acc[6]);
                acc[7] = fmaf(e[k], b4.w, acc[7]);
                acc[8] = fmaf(e[k], b8,   acc[8]);
            }
#pragma unroll
            for (int j = 0; j < 9; j++) C[j] = fmaf(fast_lg2(acc[j]), LN2, r);
        }
        __syncthreads();
        if (tid < active) {
#pragma unroll
            for (int j = 0; j < 9; j++) sMt[pp][i * 9 + j] = C[j];
        }
    }
    __syncthreads();

    if (tid < 81) g_M[(b * NQ + q) * 81 + tid] = sMt[0][tid];
    if (tid == 0) {
        atomicAdd(&g_num[b], s_accf);
        atomicAdd(&g_cnt[b], s_msum);
        __threadfence();
        int old = atomicAdd(&g_ticket[b], 1);
        s_last = (old == NQ - 1);
    }
    __syncthreads();

    if (s_last && tid < 32) {
        __threadfence();
        const long long* t64 = (const long long*)tags;
        const int*       t32 = (const int*)tags;
        const int is64 = g_tags64;

        const int j = tid;
        float v = (j < 9) ? (startT[j] + em_b[j]) : -1e30f;
        for (int c = 0; c < NQ; c++) {
            const float* Mc = g_M + (b * NQ + c) * 81;
            float vals[9];
#pragma unroll
            for (int i2 = 0; i2 < 9; i2++) {
                float sv = __shfl_sync(0xffffffffu, v, i2);
                vals[i2] = sv + ((j < 9) ? Mc[i2 * 9 + j] : 0.0f);
            }
            float nv = -1e30f;
            if (j < 9) {
                float mx = vals[0];
#pragma unroll
                for (int i2 = 1; i2 < 9; i2++) mx = fmaxf(mx, vals[i2]);
                float s = 0.0f;
#pragma unroll
                for (int i2 = 0; i2 < 9; i2++) s += fast_ex2((vals[i2] - mx) * L2E);
                nv = fmaf(fast_lg2(s), LN2, mx);
            }
            v = nv;
        }
        float x = (j < 9) ? v + endT[j] : -1e30f;
        float mx = x;
#pragma unroll
        for (int o = 16; o > 0; o >>= 1) mx = fmaxf(mx, __shfl_xor_sync(0xffffffffu, mx, o));
        float e = (j < 9) ? fast_ex2((x - mx) * L2E) : 0.0f;
#pragma unroll
        for (int o = 16; o > 0; o >>= 1) e += __shfl_xor_sync(0xffffffffu, e, o);
        if (tid == 0) {
            float den = fmaf(fast_lg2(e), LN2, mx);
            int tg0  = is64 ? (int)t64[b * SEQ] : t32[b * SEQ];
            int last = g_cnt[b] - 1;
            int tl   = is64 ? (int)t64[b * SEQ + last] : t32[b * SEQ + last];
            float num = g_num[b] + startT[tg0] + em_b[tg0] + endT[tl];
            atomicAdd(outbuf, num - den);
        }
    }
}

// ---------------------------------------------------------------------------
extern "C" void kernel_launch(void* const* d_in, const int* in_sizes, int n_in,
                              void* d_out, int out_size)
{
    const float* embed  = (const float*)d_in[0];
    const void*  tags   = d_in[1];
    const int*   mask   = (const int*)d_in[2];
    const float* W      = (const float*)d_in[3];
    const float* bias   = (const float*)d_in[4];
    const float* startT = (const float*)d_in[5];
    const float* endT   = (const float*)d_in[6];
    const float* trans  = (const float*)d_in[7];
    float* out = (float*)d_out;

    emis11<<<(BATCH * SEQ) / 32, 128>>>(embed, W, bias,
                                        (const unsigned*)tags, out);
    dim3 g2(NQ, BATCH);
    crf_scan_fin<<<g2, STH>>>(out, tags, mask, startT, endT, trans);
}